// round 3
// baseline (speedup 1.0000x reference)
#include <cuda_runtime.h>
#include <math.h>

// ---------------------------------------------------------------------------
// Multi-view edge photometric loss.
// Inputs: 0 start(N,3) 1 end(N,3) 2 imgs(5,H,W) 3 trans(S,3,4) 4 K(3,3)
//         5 coords_x(P) 6 coords_y(P) 7 edge_idx(P,i32) 8 num_per_edge(N,i32)
// coords are recomputed analytically (cx = h/(num_h-1), cy = dyTab[j]).
// Output f32: loss(S,N) | mask(S,N) | black(N) | p2d1(P,2) | p2d2(S,P,2)
// ---------------------------------------------------------------------------

#define MAXE 6144
#define NS 4
#define NHV2 20  // 2*NUM_HALF_V points per h-step

__device__ float g_params[5 * MAXE * 8];
__device__ int   g_begin[MAXE];

// ---------------- fused prep: block 0 scans, others do edge params ---------
__device__ __forceinline__ void store_prm(int cam, int e, int nE,
                                          float p0x, float p0y,
                                          float dx, float dy, float upscale)
{
    float cx = dy, cy = -dx;
    float nrm = sqrtf(cx * cx + cy * cy);
    float sc = upscale / (nrm + 1e-6f);
    float* p = &g_params[((size_t)cam * nE + e) * 8];
    p[0] = p0x; p[1] = p0y; p[2] = dx; p[3] = dy; p[4] = cx * sc; p[5] = cy * sc;
}

__global__ void prep_kernel(const int* __restrict__ npe,
                            const float* __restrict__ sp,
                            const float* __restrict__ ep,
                            const float* __restrict__ K,
                            const float* __restrict__ trans,
                            int n_edges, int num_src, float upscale)
{
    if (blockIdx.x == 0) {
        // block-wide exclusive scan of npe into g_begin (256 threads)
        __shared__ int ssum[256];
        int tid = threadIdx.x;
        int chunk = (n_edges + 255) / 256;
        int lo = min(tid * chunk, n_edges);
        int hi = min(lo + chunk, n_edges);
        int local = 0;
        for (int i = lo; i < hi; i++) local += npe[i];
        ssum[tid] = local;
        __syncthreads();
        for (int d = 1; d < 256; d <<= 1) {
            int t = (tid >= d) ? ssum[tid - d] : 0;
            __syncthreads();
            ssum[tid] += t;
            __syncthreads();
        }
        int run = ssum[tid] - local;
        for (int i = lo; i < hi; i++) { g_begin[i] = run; run += npe[i]; }
        return;
    }
    int e = (blockIdx.x - 1) * blockDim.x + threadIdx.x;
    if (e >= n_edges) return;
    float sx = sp[3 * e], sy = sp[3 * e + 1], sz = sp[3 * e + 2];
    float tx = ep[3 * e], ty = ep[3 * e + 1], tz = ep[3 * e + 2];
    {
        float pzs = K[6] * sx + K[7] * sy + K[8] * sz;
        float us  = (K[0] * sx + K[1] * sy + K[2] * sz) / (pzs + 1e-6f);
        float vs  = (K[3] * sx + K[4] * sy + K[5] * sz) / (pzs + 1e-6f);
        float pzt = K[6] * tx + K[7] * ty + K[8] * tz;
        float ut  = (K[0] * tx + K[1] * ty + K[2] * tz) / (pzt + 1e-6f);
        float vt  = (K[3] * tx + K[4] * ty + K[5] * tz) / (pzt + 1e-6f);
        store_prm(0, e, n_edges, us, vs, ut - us, vt - vs, upscale);
    }
    for (int s = 0; s < num_src; s++) {
        const float* T = trans + 12 * s;
        float pzs = T[8] * sx + T[9] * sy + T[10] * sz + T[11];
        float us  = (T[0] * sx + T[1] * sy + T[2] * sz + T[3]) / (pzs + 1e-6f);
        float vs  = (T[4] * sx + T[5] * sy + T[6] * sz + T[7]) / (pzs + 1e-6f);
        float pzt = T[8] * tx + T[9] * ty + T[10] * tz + T[11];
        float ut  = (T[0] * tx + T[1] * ty + T[2] * tz + T[3]) / (pzt + 1e-6f);
        float vt  = (T[4] * tx + T[5] * ty + T[6] * tz + T[7]) / (pzt + 1e-6f);
        store_prm(1 + s, e, n_edges, us, vs, ut - us, vt - vs, upscale);
    }
}

// --------------------------- bilinear sample -------------------------------
__device__ __forceinline__ float bilerp(const float* __restrict__ img,
                                        float u, float v, int W, int H)
{
    float x = u * (float)W - 0.5f;
    float y = v * (float)H - 0.5f;
    float x0f = floorf(x), y0f = floorf(y);
    float wx = x - x0f, wy = y - y0f;
    int x0i = min(max((int)x0f, 0), W - 1);
    int x1i = min(x0i + 1, W - 1);
    int y0i = min(max((int)y0f, 0), H - 1);
    int y1i = min(y0i + 1, H - 1);
    const float* r0 = img + (size_t)y0i * W;
    const float* r1 = img + (size_t)y1i * W;
    float v00 = __ldg(r0 + x0i), v01 = __ldg(r0 + x1i);
    float v10 = __ldg(r1 + x0i), v11 = __ldg(r1 + x1i);
    float top = v00 * (1.0f - wx) + v01 * wx;
    float bot = v10 * (1.0f - wx) + v11 * wx;
    return top * (1.0f - wy) + bot * wy;
}

// ----------------- point kernel: block/edge, 4 points/thread ---------------
__global__ void __launch_bounds__(256)
point_kernel(const float* __restrict__ imgs,
             const int* __restrict__ npe,
             float* __restrict__ out_loss, float* __restrict__ out_mask,
             float* __restrict__ out_black,
             float* __restrict__ out_p2d1, float* __restrict__ out_p2d2,
             int W, int H, int n_edges, int P)
{
    int e = blockIdx.x;
    int tid = threadIdx.x;

    __shared__ float dytab[NHV2];
    __shared__ float redf[8][5];
    __shared__ unsigned redm[8];
    if (tid < NHV2) {
        int j = tid;
        float num = (float)((j < 10) ? (j - 9) : (j - 10));
        dytab[j] = num / 9.0f;
    }
    __syncthreads();

    // per-camera params into registers (uniform across block -> L1 broadcast)
    float prm[5][6];
#pragma unroll
    for (int c = 0; c < 5; c++) {
        const float* p = &g_params[((size_t)c * n_edges + e) * 8];
#pragma unroll
        for (int j = 0; j < 6; j++) prm[c][j] = __ldg(p + j);
    }

    int b = g_begin[e];
    int n = npe[e];
    int nh1 = n / NHV2 - 1;              // num_h - 1 (>= 1)
    float inv_nh1 = 1.0f / (float)nh1;
    const size_t imgHW = (size_t)W * H;

    float ls[NS] = {0.f, 0.f, 0.f, 0.f};
    float bc = 0.f;
    unsigned m = (1u << NS) - 1u;

    float4* o1 = reinterpret_cast<float4*>(out_p2d1);
    float4* o2 = reinterpret_cast<float4*>(out_p2d2);

    int nq = n >> 2;  // n % 4 == 0 always (multiple of 20)
    for (int q = tid; q < nq; q += blockDim.x) {
        int l0 = q << 2;
        int p0 = b + l0;

        float cx[4], cy[4];
#pragma unroll
        for (int k = 0; k < 4; k++) {
            int l = l0 + k;
            int h = l / NHV2;
            int j = l - h * NHV2;
            cx[k] = (float)h * inv_nh1;
            cy[k] = dytab[j];
        }

        // reference camera
        float s1v[4], u1c[4], v1c[4];
        bool vm1[4];
#pragma unroll
        for (int k = 0; k < 4; k++) {
            float u = fmaf(prm[0][2], cx[k], fmaf(prm[0][4], cy[k], prm[0][0]));
            float v = fmaf(prm[0][3], cx[k], fmaf(prm[0][5], cy[k], prm[0][1]));
            vm1[k] = (u > 0.f) & (u < 1.f) & (v > 0.f) & (v < 1.f);
            u1c[k] = fminf(fmaxf(u, 0.f), 0.999999f);
            v1c[k] = fminf(fmaxf(v, 0.f), 0.999999f);
        }
        o1[(p0 >> 1) + 0] = make_float4(u1c[0], v1c[0], u1c[1], v1c[1]);
        o1[(p0 >> 1) + 1] = make_float4(u1c[2], v1c[2], u1c[3], v1c[3]);
#pragma unroll
        for (int k = 0; k < 4; k++) {
            s1v[k] = bilerp(imgs, u1c[k], v1c[k], W, H);
            if (s1v[k] < 0.01f) bc += 1.f;
        }

#pragma unroll
        for (int s = 0; s < NS; s++) {
            float uc[4], vc[4];
            bool ok[4];
#pragma unroll
            for (int k = 0; k < 4; k++) {
                float u = fmaf(prm[s + 1][2], cx[k], fmaf(prm[s + 1][4], cy[k], prm[s + 1][0]));
                float v = fmaf(prm[s + 1][3], cx[k], fmaf(prm[s + 1][5], cy[k], prm[s + 1][1]));
                ok[k] = vm1[k] & (u > 0.f) & (u < 1.f) & (v > 0.f) & (v < 1.f);
                uc[k] = fminf(fmaxf(u, 0.f), 0.999999f);
                vc[k] = fminf(fmaxf(v, 0.f), 0.999999f);
            }
            size_t base = ((size_t)s * P + p0) >> 1;
            o2[base + 0] = make_float4(uc[0], vc[0], uc[1], vc[1]);
            o2[base + 1] = make_float4(uc[2], vc[2], uc[3], vc[3]);
            const float* img = imgs + (size_t)(s + 1) * imgHW;
#pragma unroll
            for (int k = 0; k < 4; k++) {
                float s2 = bilerp(img, uc[k], vc[k], W, H);
                float d = s2 - s1v[k];
                ls[s] += d * d;
                if (!ok[k]) m &= ~(1u << s);
            }
        }
    }

    // warp + block reduce
#pragma unroll
    for (int off = 16; off > 0; off >>= 1) {
#pragma unroll
        for (int s = 0; s < NS; s++) ls[s] += __shfl_down_sync(0xFFFFFFFFu, ls[s], off);
        bc += __shfl_down_sync(0xFFFFFFFFu, bc, off);
        m &= __shfl_down_sync(0xFFFFFFFFu, m, off);
    }
    int lane = tid & 31, warp = tid >> 5;
    if (lane == 0) {
#pragma unroll
        for (int s = 0; s < NS; s++) redf[warp][s] = ls[s];
        redf[warp][4] = bc;
        redm[warp] = m;
    }
    __syncthreads();
    if (tid == 0) {
        float tls[NS] = {0.f, 0.f, 0.f, 0.f};
        float tbc = 0.f;
        unsigned tm = (1u << NS) - 1u;
        for (int w = 0; w < 8; w++) {
#pragma unroll
            for (int s = 0; s < NS; s++) tls[s] += redf[w][s];
            tbc += redf[w][4];
            tm &= redm[w];
        }
        float cnt = (float)n;
#pragma unroll
        for (int s = 0; s < NS; s++) {
            out_loss[(size_t)s * n_edges + e] = tls[s] / cnt;
            out_mask[(size_t)s * n_edges + e] = ((tm >> s) & 1u) ? 1.f : 0.f;
        }
        out_black[e] = ((tbc / cnt) > 0.5f) ? 1.f : 0.f;
    }
}

// ---------------------------------------------------------------------------
extern "C" void kernel_launch(void* const* d_in, const int* in_sizes, int n_in,
                              void* d_out, int out_size)
{
    const float* start = (const float*)d_in[0];
    const float* end_p = (const float*)d_in[1];
    const float* imgs  = (const float*)d_in[2];
    const float* trans = (const float*)d_in[3];
    const float* K     = (const float*)d_in[4];
    const int*   npe   = (const int*)d_in[8];
    float* out = (float*)d_out;

    int n_edges = in_sizes[0] / 3;
    int P       = in_sizes[5];
    int num_src = in_sizes[3] / 12;  // 4
    long long hw = (long long)in_sizes[2] / (num_src + 1);
    int W = (int)(sqrt((double)hw) + 0.5);
    int H = (int)(hw / W);

    float* out_loss  = out;
    float* out_mask  = out_loss + (size_t)num_src * n_edges;
    float* out_black = out_mask + (size_t)num_src * n_edges;
    float* out_p2d1  = out_black + n_edges;
    float* out_p2d2  = out_p2d1 + 2 * (size_t)P;

    int prep_blocks = 1 + (n_edges + 255) / 256;
    prep_kernel<<<prep_blocks, 256>>>(npe, start, end_p, K, trans,
                                      n_edges, num_src, 10.0f / (float)W);
    point_kernel<<<n_edges, 256>>>(imgs, npe,
                                   out_loss, out_mask, out_black,
                                   out_p2d1, out_p2d2,
                                   W, H, n_edges, P);
}

// round 4
// speedup vs baseline: 1.4249x; 1.4249x over previous
#include <cuda_runtime.h>
#include <math.h>

// ---------------------------------------------------------------------------
// Multi-view edge photometric loss.
// Inputs: 0 start(N,3) 1 end(N,3) 2 imgs(5,H,W) 3 trans(S,3,4) 4 K(3,3)
//         5 coords_x(P) 6 coords_y(P) 7 edge_idx(P,i32) 8 num_per_edge(N,i32)
// coords recomputed analytically. Output f32:
//  loss(S,N) | mask(S,N) | black(N) | p2d1(P,2) | p2d2(S,P,2)
// ---------------------------------------------------------------------------

#define MAXE 6144
#define NS 4
#define NHV2 20

__device__ float g_params[5 * MAXE * 8];
__device__ int   g_begin[MAXE];

// ---------------- fused prep: block 0 scans, others do edge params ---------
__device__ __forceinline__ void store_prm(int cam, int e, int nE,
                                          float p0x, float p0y,
                                          float dx, float dy, float upscale)
{
    float cx = dy, cy = -dx;
    float nrm = sqrtf(cx * cx + cy * cy);
    float sc = upscale / (nrm + 1e-6f);
    float* p = &g_params[((size_t)cam * nE + e) * 8];
    p[0] = p0x; p[1] = p0y; p[2] = dx; p[3] = dy; p[4] = cx * sc; p[5] = cy * sc;
}

__global__ void prep_kernel(const int* __restrict__ npe,
                            const float* __restrict__ sp,
                            const float* __restrict__ ep,
                            const float* __restrict__ K,
                            const float* __restrict__ trans,
                            int n_edges, int num_src, float upscale)
{
    if (blockIdx.x == 0) {
        __shared__ int ssum[256];
        int tid = threadIdx.x;
        int chunk = (n_edges + 255) / 256;
        int lo = min(tid * chunk, n_edges);
        int hi = min(lo + chunk, n_edges);
        int local = 0;
        for (int i = lo; i < hi; i++) local += npe[i];
        ssum[tid] = local;
        __syncthreads();
        for (int d = 1; d < 256; d <<= 1) {
            int t = (tid >= d) ? ssum[tid - d] : 0;
            __syncthreads();
            ssum[tid] += t;
            __syncthreads();
        }
        int run = ssum[tid] - local;
        for (int i = lo; i < hi; i++) { g_begin[i] = run; run += npe[i]; }
        return;
    }
    int e = (blockIdx.x - 1) * blockDim.x + threadIdx.x;
    if (e >= n_edges) return;
    float sx = sp[3 * e], sy = sp[3 * e + 1], sz = sp[3 * e + 2];
    float tx = ep[3 * e], ty = ep[3 * e + 1], tz = ep[3 * e + 2];
    {
        float pzs = K[6] * sx + K[7] * sy + K[8] * sz;
        float us  = (K[0] * sx + K[1] * sy + K[2] * sz) / (pzs + 1e-6f);
        float vs  = (K[3] * sx + K[4] * sy + K[5] * sz) / (pzs + 1e-6f);
        float pzt = K[6] * tx + K[7] * ty + K[8] * tz;
        float ut  = (K[0] * tx + K[1] * ty + K[2] * tz) / (pzt + 1e-6f);
        float vt  = (K[3] * tx + K[4] * ty + K[5] * tz) / (pzt + 1e-6f);
        store_prm(0, e, n_edges, us, vs, ut - us, vt - vs, upscale);
    }
    for (int s = 0; s < num_src; s++) {
        const float* T = trans + 12 * s;
        float pzs = T[8] * sx + T[9] * sy + T[10] * sz + T[11];
        float us  = (T[0] * sx + T[1] * sy + T[2] * sz + T[3]) / (pzs + 1e-6f);
        float vs  = (T[4] * sx + T[5] * sy + T[6] * sz + T[7]) / (pzs + 1e-6f);
        float pzt = T[8] * tx + T[9] * ty + T[10] * tz + T[11];
        float ut  = (T[0] * tx + T[1] * ty + T[2] * tz + T[3]) / (pzt + 1e-6f);
        float vt  = (T[4] * tx + T[5] * ty + T[6] * tz + T[7]) / (pzt + 1e-6f);
        store_prm(1 + s, e, n_edges, us, vs, ut - us, vt - vs, upscale);
    }
}

// --------------------------- bilinear sample -------------------------------
__device__ __forceinline__ float bilerp(const float* __restrict__ img,
                                        float u, float v, int W, int H)
{
    float x = u * (float)W - 0.5f;
    float y = v * (float)H - 0.5f;
    float x0f = floorf(x), y0f = floorf(y);
    float wx = x - x0f, wy = y - y0f;
    int x0i = min(max((int)x0f, 0), W - 1);
    int x1i = min(x0i + 1, W - 1);
    int y0i = min(max((int)y0f, 0), H - 1);
    int y1i = min(y0i + 1, H - 1);
    const float* r0 = img + (size_t)y0i * W;
    const float* r1 = img + (size_t)y1i * W;
    float v00 = __ldg(r0 + x0i), v01 = __ldg(r0 + x1i);
    float v10 = __ldg(r1 + x0i), v11 = __ldg(r1 + x1i);
    float top = fmaf(wx, v01 - v00, v00);
    float bot = fmaf(wx, v11 - v10, v10);
    return fmaf(wy, bot - top, top);
}

// ----------- point kernel: block/edge, 128 thr, 2 points/thread ------------
__global__ void __launch_bounds__(128, 8)
point_kernel(const float* __restrict__ imgs,
             const int* __restrict__ npe,
             float* __restrict__ out_loss, float* __restrict__ out_mask,
             float* __restrict__ out_black,
             float* __restrict__ out_p2d1, float* __restrict__ out_p2d2,
             int W, int H, int n_edges, int P)
{
    int e = blockIdx.x;
    int tid = threadIdx.x;

    __shared__ float redf[4][5];
    __shared__ unsigned redm[4];

    // per-camera params (uniform across block)
    float prm[5][6];
#pragma unroll
    for (int c = 0; c < 5; c++) {
        const float* p = &g_params[((size_t)c * n_edges + e) * 8];
#pragma unroll
        for (int j = 0; j < 6; j++) prm[c][j] = __ldg(p + j);
    }

    int b = g_begin[e];
    int n = npe[e];
    float inv_nh1 = 1.0f / (float)(n / NHV2 - 1);
    const size_t imgHW = (size_t)W * H;

    float ls0 = 0.f, ls1 = 0.f, ls2 = 0.f, ls3 = 0.f;
    float bc = 0.f;
    unsigned m = (1u << NS) - 1u;

    float4* o1 = reinterpret_cast<float4*>(out_p2d1) + (b >> 1);
    float4* o2 = reinterpret_cast<float4*>(out_p2d2) + (b >> 1);
    size_t strideP = (size_t)P >> 1;

    int npair = n >> 1;  // n multiple of 20
    for (int r = tid; r < npair; r += 128) {
        int h  = r / 10;          // h-step (both points of the pair share it)
        int jj = r - h * 10;      // pair index within h-step (j = 2jj, 2jj+1)
        float cx = (float)h * inv_nh1;
        float base = (float)(2 * jj + ((jj < 5) ? -9 : -10));
        float cy0 = base * (1.0f / 9.0f);
        float cy1 = (base + 1.0f) * (1.0f / 9.0f);

        // reference camera
        float u0 = fmaf(prm[0][2], cx, fmaf(prm[0][4], cy0, prm[0][0]));
        float v0 = fmaf(prm[0][3], cx, fmaf(prm[0][5], cy0, prm[0][1]));
        float u1 = fmaf(prm[0][2], cx, fmaf(prm[0][4], cy1, prm[0][0]));
        float v1 = fmaf(prm[0][3], cx, fmaf(prm[0][5], cy1, prm[0][1]));
        bool vm1a = (u0 > 0.f) & (u0 < 1.f) & (v0 > 0.f) & (v0 < 1.f);
        bool vm1b = (u1 > 0.f) & (u1 < 1.f) & (v1 > 0.f) & (v1 < 1.f);
        u0 = fminf(fmaxf(u0, 0.f), 0.999999f);
        v0 = fminf(fmaxf(v0, 0.f), 0.999999f);
        u1 = fminf(fmaxf(u1, 0.f), 0.999999f);
        v1 = fminf(fmaxf(v1, 0.f), 0.999999f);
        o1[r] = make_float4(u0, v0, u1, v1);
        float s1a = bilerp(imgs, u0, v0, W, H);
        float s1b = bilerp(imgs, u1, v1, W, H);
        if (s1a < 0.01f) bc += 1.f;
        if (s1b < 0.01f) bc += 1.f;

#pragma unroll
        for (int s = 0; s < NS; s++) {
            float ua = fmaf(prm[s + 1][2], cx, fmaf(prm[s + 1][4], cy0, prm[s + 1][0]));
            float va = fmaf(prm[s + 1][3], cx, fmaf(prm[s + 1][5], cy0, prm[s + 1][1]));
            float ub = fmaf(prm[s + 1][2], cx, fmaf(prm[s + 1][4], cy1, prm[s + 1][0]));
            float vb = fmaf(prm[s + 1][3], cx, fmaf(prm[s + 1][5], cy1, prm[s + 1][1]));
            bool oka = vm1a & (ua > 0.f) & (ua < 1.f) & (va > 0.f) & (va < 1.f);
            bool okb = vm1b & (ub > 0.f) & (ub < 1.f) & (vb > 0.f) & (vb < 1.f);
            ua = fminf(fmaxf(ua, 0.f), 0.999999f);
            va = fminf(fmaxf(va, 0.f), 0.999999f);
            ub = fminf(fmaxf(ub, 0.f), 0.999999f);
            vb = fminf(fmaxf(vb, 0.f), 0.999999f);
            o2[(size_t)s * strideP + r] = make_float4(ua, va, ub, vb);
            const float* img = imgs + (size_t)(s + 1) * imgHW;
            float s2a = bilerp(img, ua, va, W, H);
            float s2b = bilerp(img, ub, vb, W, H);
            float da = s2a - s1a;
            float db = s2b - s1b;
            float acc = fmaf(da, da, db * db);
            if (s == 0) ls0 += acc;
            else if (s == 1) ls1 += acc;
            else if (s == 2) ls2 += acc;
            else ls3 += acc;
            if (!(oka && okb)) m &= ~(1u << s);
        }
    }

    // warp + block reduce
#pragma unroll
    for (int off = 16; off > 0; off >>= 1) {
        ls0 += __shfl_down_sync(0xFFFFFFFFu, ls0, off);
        ls1 += __shfl_down_sync(0xFFFFFFFFu, ls1, off);
        ls2 += __shfl_down_sync(0xFFFFFFFFu, ls2, off);
        ls3 += __shfl_down_sync(0xFFFFFFFFu, ls3, off);
        bc  += __shfl_down_sync(0xFFFFFFFFu, bc, off);
        m   &= __shfl_down_sync(0xFFFFFFFFu, m, off);
    }
    int lane = tid & 31, warp = tid >> 5;
    if (lane == 0) {
        redf[warp][0] = ls0; redf[warp][1] = ls1;
        redf[warp][2] = ls2; redf[warp][3] = ls3;
        redf[warp][4] = bc;
        redm[warp] = m;
    }
    __syncthreads();
    if (tid == 0) {
        float tls[NS] = {0.f, 0.f, 0.f, 0.f};
        float tbc = 0.f;
        unsigned tm = (1u << NS) - 1u;
        for (int w = 0; w < 4; w++) {
#pragma unroll
            for (int s = 0; s < NS; s++) tls[s] += redf[w][s];
            tbc += redf[w][4];
            tm &= redm[w];
        }
        float cnt = (float)n;
#pragma unroll
        for (int s = 0; s < NS; s++) {
            out_loss[(size_t)s * n_edges + e] = tls[s] / cnt;
            out_mask[(size_t)s * n_edges + e] = ((tm >> s) & 1u) ? 1.f : 0.f;
        }
        out_black[e] = ((tbc / cnt) > 0.5f) ? 1.f : 0.f;
    }
}

// ---------------------------------------------------------------------------
extern "C" void kernel_launch(void* const* d_in, const int* in_sizes, int n_in,
                              void* d_out, int out_size)
{
    const float* start = (const float*)d_in[0];
    const float* end_p = (const float*)d_in[1];
    const float* imgs  = (const float*)d_in[2];
    const float* trans = (const float*)d_in[3];
    const float* K     = (const float*)d_in[4];
    const int*   npe   = (const int*)d_in[8];
    float* out = (float*)d_out;

    int n_edges = in_sizes[0] / 3;
    int P       = in_sizes[5];
    int num_src = in_sizes[3] / 12;  // 4
    long long hw = (long long)in_sizes[2] / (num_src + 1);
    int W = (int)(sqrt((double)hw) + 0.5);
    int H = (int)(hw / W);

    float* out_loss  = out;
    float* out_mask  = out_loss + (size_t)num_src * n_edges;
    float* out_black = out_mask + (size_t)num_src * n_edges;
    float* out_p2d1  = out_black + n_edges;
    float* out_p2d2  = out_p2d1 + 2 * (size_t)P;

    int prep_blocks = 1 + (n_edges + 255) / 256;
    prep_kernel<<<prep_blocks, 256>>>(npe, start, end_p, K, trans,
                                      n_edges, num_src, 10.0f / (float)W);
    point_kernel<<<n_edges, 128>>>(imgs, npe,
                                   out_loss, out_mask, out_black,
                                   out_p2d1, out_p2d2,
                                   W, H, n_edges, P);
}